// round 13
// baseline (speedup 1.0000x reference)
#include <cuda_runtime.h>
#include <cuda_fp16.h>

#define N_NODES   50000
#define N_PAIRS   800000
#define TILE_M    128
#define N_TILES   (N_PAIRS / TILE_M)       // 6250

// ---------------- main-kernel SMEM layout ----------------
#define PITCH     528                       // bytes per A row (256 halves + 8 pad)
#define SM_A      0                         // 128*528 = 67584 ; reused as out staging
#define SM_B      67584
#define BUF       8448                      // 16 rows * 528
#define NGROUP    16                        // 16 groups of 2 chunks (32 N-rows each)
#define OPITCH    68                        // out staging pitch in floats (272B, 16-aligned)
#define SM_SIZE   (67584 + 4 * BUF)         // 101376 -> occ 2

// ---------------- device scratch ----------------
__device__ __align__(16) __half g_q[(size_t)N_NODES * 256];   // p1 @ W1, fp16
__device__ __align__(16) __half g_w2t[512 * 256];             // W2^T as [n][k] fp16

// ---------------- helpers ----------------
__device__ __forceinline__ unsigned smem_u32(const void* p) {
    unsigned a;
    asm("{ .reg .u64 t; cvta.to.shared.u64 t, %1; cvt.u32.u64 %0, t; }" : "=r"(a) : "l"(p));
    return a;
}

__device__ __forceinline__ void ldmx4(unsigned* r, unsigned addr) {
    asm volatile("ldmatrix.sync.aligned.m8n8.x4.shared.b16 {%0,%1,%2,%3}, [%4];"
                 : "=r"(r[0]), "=r"(r[1]), "=r"(r[2]), "=r"(r[3]) : "r"(addr));
}

// fp16-accumulate HMMA, accumulate into c
__device__ __forceinline__ void mma16816h(unsigned* c, const unsigned* a, unsigned b0, unsigned b1) {
    asm volatile("mma.sync.aligned.m16n8k16.row.col.f16.f16.f16.f16 "
                 "{%0,%1}, {%2,%3,%4,%5}, {%6,%7}, {%0,%1};"
                 : "+r"(c[0]), "+r"(c[1])
                 : "r"(a[0]), "r"(a[1]), "r"(a[2]), "r"(a[3]), "r"(b0), "r"(b1));
}
// fp16-accumulate HMMA, C = 0 (segment init)
__device__ __forceinline__ void mma16816h_z(unsigned* d, const unsigned* a, unsigned b0, unsigned b1) {
    asm volatile("mma.sync.aligned.m16n8k16.row.col.f16.f16.f16.f16 "
                 "{%0,%1}, {%2,%3,%4,%5}, {%6,%7}, {%8,%8};"
                 : "=r"(d[0]), "=r"(d[1])
                 : "r"(a[0]), "r"(a[1]), "r"(a[2]), "r"(a[3]), "r"(b0), "r"(b1), "r"(0u));
}

__device__ __forceinline__ float tanh_approx(float x) {
    float r;
    asm("tanh.approx.f32 %0, %1;" : "=f"(r) : "f"(x));
    return r;
}

#define CP16(sm, g)  asm volatile("cp.async.cg.shared.global [%0], [%1], 16;" :: "r"(sm), "l"(g) : "memory")
#define CP_COMMIT()  asm volatile("cp.async.commit_group;" ::: "memory")
#define CP_WAIT0()   asm volatile("cp.async.wait_group 0;" ::: "memory")

// ---------------- kernel A: q = p1 @ W1 (fp32 math, fp16 store) + W2 prep ----------------
__global__ __launch_bounds__(256) void pil_q(const float* __restrict__ p1,
                                             const float* __restrict__ W1,
                                             const float* __restrict__ W2,
                                             __half* __restrict__ q) {
    __shared__ float sA[64 * 68];
    __shared__ float sB[64 * 68];
    int tid = threadIdx.x;
    int m0 = blockIdx.x * 64, n0 = blockIdx.y * 64;

    // fold W2^T fp16 conversion into this kernel (y==0 stripe covers all 131072 elems)
    if (blockIdx.y == 0) {
        int t = blockIdx.x * 256 + tid;            // gridDim.x*256 = 200192 >= 131072
        if (t < 512 * 256) {
            int k = t >> 9, n = t & 511;
            g_w2t[n * 256 + k] = __float2half_rn(W2[t]);
        }
    }

    #pragma unroll
    for (int i = 0; i < 4; i++) {
        int v = tid + i * 256;
        int r = v >> 4, c4 = (v & 15) * 4;
        float4 av = make_float4(0.f, 0.f, 0.f, 0.f);
        if (m0 + r < N_NODES) av = *(const float4*)(p1 + (long)(m0 + r) * 64 + c4);
        *(float4*)(sA + r * 68 + c4) = av;
        *(float4*)(sB + r * 68 + c4) = *(const float4*)(W1 + (long)r * 256 + n0 + c4);
    }
    __syncthreads();

    int tx = tid & 15, ty = tid >> 4;
    float c[4][4];
    #pragma unroll
    for (int i = 0; i < 4; i++)
        #pragma unroll
        for (int j = 0; j < 4; j++) c[i][j] = 0.f;

    #pragma unroll 8
    for (int k = 0; k < 64; k++) {
        float4 b = *(float4*)(sB + k * 68 + tx * 4);
        #pragma unroll
        for (int i = 0; i < 4; i++) {
            float a = sA[(ty * 4 + i) * 68 + k];
            c[i][0] = fmaf(a, b.x, c[i][0]);
            c[i][1] = fmaf(a, b.y, c[i][1]);
            c[i][2] = fmaf(a, b.z, c[i][2]);
            c[i][3] = fmaf(a, b.w, c[i][3]);
        }
    }
    #pragma unroll
    for (int i = 0; i < 4; i++) {
        int m = m0 + ty * 4 + i;
        if (m < N_NODES) {
            __half2 h01 = __floats2half2_rn(c[i][0], c[i][1]);
            __half2 h23 = __floats2half2_rn(c[i][2], c[i][3]);
            uint2 o;
            o.x = *(unsigned*)&h01;
            o.y = *(unsigned*)&h23;
            *(uint2*)(q + (long)m * 256 + n0 + tx * 4) = o;
        }
    }
}

// ---------------- main: gather + tanh + GEMM2 + basis einsum ----------------
// 128 threads / 4 warps; each warp owns 32 pair-rows (2 m16 tiles).
// fp16-accum HMMA chained over K=64 segments, promoted to fp32.
__global__ __launch_bounds__(128, 2) void pil_main(const void* __restrict__ pi,
                                                   const void* __restrict__ pj,
                                                   const float* __restrict__ basis,
                                                   float* __restrict__ out) {
    extern __shared__ char smem[];
    unsigned sb = smem_u32(smem);
    float* outS = (float*)smem;               // overlays A region (pitch OPITCH floats)
    int tid  = threadIdx.x;
    int w    = tid >> 5;
    int l    = tid & 31;
    long pairbase = (long)blockIdx.x * TILE_M;

    // -- prefetch W2 group 0 (rows 0..31) immediately --
    {
        #pragma unroll
        for (int i = 0; i < 8; i++) {
            int v = tid + i * 128;                    // 0..1023
            int r = v >> 5, seg = (v & 31) * 16;
            CP16(sb + SM_B + r * PITCH + seg, (const char*)g_w2t + (long)r * 512 + seg);
        }
        CP_COMMIT();
    }

    // -- index dtype sniff (int64 vs silently-int32) --
    bool is64;
    {
        const unsigned* wds = (const unsigned*)pi;
        unsigned acc = 0;
        #pragma unroll
        for (int u = 1; u < 32; u += 2) acc |= wds[u];
        is64 = (acc == 0);
    }

    // -- basis fragments for epilogue: 4 rows per lane (2 m-tiles x 2 row-halves) --
    int r0 = 32 * w + (l >> 2);                 // m-tile 0, first half
    int s  = l & 3;
    float2 basA0 = *(const float2*)(basis + (pairbase + r0) * 8 + 2 * s);
    float2 basB0 = *(const float2*)(basis + (pairbase + r0 + 8) * 8 + 2 * s);
    float2 basA1 = *(const float2*)(basis + (pairbase + r0 + 16) * 8 + 2 * s);
    float2 basB1 = *(const float2*)(basis + (pairbase + r0 + 24) * 8 + 2 * s);

    // -- phase 1: gather q row (fp16), tanh.approx -> SMEM A (1 row / thread) --
    {
        int row = tid;
        long p = pairbase + row;
        long ii, jj;
        if (is64) { ii = ((const long long*)pi)[p]; jj = ((const long long*)pj)[p]; }
        else      { ii = ((const int*)pi)[p];       jj = ((const int*)pj)[p]; }
        const uint4* qi = (const uint4*)(g_q + (size_t)ii * 256);
        const uint4* qj = (const uint4*)(g_q + (size_t)jj * 256);
        char* dst = smem + row * PITCH;
        #pragma unroll 4
        for (int j = 0; j < 32; j++) {
            uint4 A = qi[j], B = qj[j];
            uint4 O;
            {
                float2 fa = __half22float2(*(__half2*)&A.x), fb = __half22float2(*(__half2*)&B.x);
                __half2 h = __floats2half2_rn(tanh_approx(fa.x + fb.x), tanh_approx(fa.y + fb.y));
                O.x = *(unsigned*)&h;
            }
            {
                float2 fa = __half22float2(*(__half2*)&A.y), fb = __half22float2(*(__half2*)&B.y);
                __half2 h = __floats2half2_rn(tanh_approx(fa.x + fb.x), tanh_approx(fa.y + fb.y));
                O.y = *(unsigned*)&h;
            }
            {
                float2 fa = __half22float2(*(__half2*)&A.z), fb = __half22float2(*(__half2*)&B.z);
                __half2 h = __floats2half2_rn(tanh_approx(fa.x + fb.x), tanh_approx(fa.y + fb.y));
                O.z = *(unsigned*)&h;
            }
            {
                float2 fa = __half22float2(*(__half2*)&A.w), fb = __half22float2(*(__half2*)&B.w);
                __half2 h = __floats2half2_rn(tanh_approx(fa.x + fb.x), tanh_approx(fa.y + fb.y));
                O.w = *(unsigned*)&h;
            }
            *(uint4*)(dst + j * 16) = O;
        }
    }
    __syncwarp();   // warp w wrote rows 32w..32w+31 == exactly its own A rows

    // -- load A fragments for both m-tiles into registers (128 regs/thread) --
    unsigned a0[16][4], a1[16][4];
    {
        unsigned rowA = 32 * w + (l & 7) + ((l >> 3) & 1) * 8;
        unsigned colA = (l >> 4) * 16;
        unsigned aBase = sb + rowA * PITCH + colA;
        #pragma unroll
        for (int ks = 0; ks < 16; ks++) ldmx4(a0[ks], aBase + ks * 32);
        #pragma unroll
        for (int ks = 0; ks < 16; ks++) ldmx4(a1[ks], aBase + 16 * PITCH + ks * 32);
    }

    // -- per-lane B ldmatrix base --
    unsigned rowBl = (l & 7) + (l >> 4) * 8;
    unsigned colBl = ((l >> 3) & 1) * 16;
    unsigned bLane = rowBl * PITCH + colBl;

    // -- phase 2: 16 groups of 2 chunks (32 N-rows), distance-1 double buffer --
    for (int it = 0; it < NGROUP; it++) {
        CP_WAIT0();               // group it resident
        __syncthreads();          // ... and other buffer pair free

        if (it + 1 < NGROUP) {    // prefetch group it+1 into the other buffer pair
            unsigned dst = sb + SM_B + ((it + 1) & 1) * (2 * BUF);
            const char* src = (const char*)g_w2t + (long)(it + 1) * 32 * 512;
            #pragma unroll
            for (int i = 0; i < 8; i++) {
                int v = tid + i * 128;                // 0..1023
                int r = v >> 5, seg = (v & 31) * 16;
                CP16(dst + r * PITCH + seg, src + (long)r * 512 + seg);
            }
            CP_COMMIT();
        }

        unsigned bBase0 = sb + SM_B + (it & 1) * (2 * BUF) + bLane;
        unsigned bBase1 = bBase0 + BUF;
        float acc0[4][4], acc1[4][4];                 // fp32 accumulators
        #pragma unroll
        for (int n = 0; n < 4; n++)
            #pragma unroll
            for (int j = 0; j < 4; j++) { acc0[n][j] = 0.f; acc1[n][j] = 0.f; }

        // 4 segments of K=64: fp16 accumulate 4 HMMAs, then promote to fp32
        #pragma unroll
        for (int sg = 0; sg < 4; sg++) {
            unsigned ch0[4][2], ch1[4][2];            // fp16 accumulators
            {   // kk = 0: init (C = 0)
                int ks = sg * 4;
                unsigned b0[4], b1[4];
                ldmx4(b0, bBase0 + ks * 32);
                ldmx4(b1, bBase1 + ks * 32);
                mma16816h_z(ch0[0], a0[ks], b0[0], b0[1]);
                mma16816h_z(ch0[1], a0[ks], b0[2], b0[3]);
                mma16816h_z(ch0[2], a0[ks], b1[0], b1[1]);
                mma16816h_z(ch0[3], a0[ks], b1[2], b1[3]);
                mma16816h_z(ch1[0], a1[ks], b0[0], b0[1]);
                mma16816h_z(ch1[1], a1[ks], b0[2], b0[3]);
                mma16816h_z(ch1[2], a1[ks], b1[0], b1[1]);
                mma16816h_z(ch1[3], a1[ks], b1[2], b1[3]);
            }
            #pragma unroll
            for (int kk = 1; kk < 4; kk++) {
                int ks = sg * 4 + kk;
                unsigned b0[4], b1[4];
                ldmx4(b0, bBase0 + ks * 32);
                ldmx4(b1, bBase1 + ks * 32);
                mma16816h(ch0[0], a0[ks], b0[0], b0[1]);
                mma16816h(ch0[1], a0[ks], b0[2], b0[3]);
                mma16816h(ch0[2], a0[ks], b1[0], b1[1]);
                mma16816h(ch0[3], a0[ks], b1[2], b1[3]);
                mma16816h(ch1[0], a1[ks], b0[0], b0[1]);
                mma16816h(ch1[1], a1[ks], b0[2], b0[3]);
                mma16816h(ch1[2], a1[ks], b1[0], b1[1]);
                mma16816h(ch1[3], a1[ks], b1[2], b1[3]);
            }
            // promote fp16 partials into fp32 accumulators
            #pragma unroll
            for (int nt = 0; nt < 4; nt++) {
                float2 f;
                f = __half22float2(*(__half2*)&ch0[nt][0]); acc0[nt][0] += f.x; acc0[nt][1] += f.y;
                f = __half22float2(*(__half2*)&ch0[nt][1]); acc0[nt][2] += f.x; acc0[nt][3] += f.y;
                f = __half22float2(*(__half2*)&ch1[nt][0]); acc1[nt][0] += f.x; acc1[nt][1] += f.y;
                f = __half22float2(*(__half2*)&ch1[nt][1]); acc1[nt][2] += f.x; acc1[nt][3] += f.y;
            }
        }

        // epilogue: fold basis, reduce lane quads, stage into outS (A region, now dead)
        #pragma unroll
        for (int nt = 0; nt < 4; nt++) {
            float u0 = acc0[nt][0] * basA0.x + acc0[nt][1] * basA0.y;
            float u1 = acc0[nt][2] * basB0.x + acc0[nt][3] * basB0.y;
            float u2 = acc1[nt][0] * basA1.x + acc1[nt][1] * basA1.y;
            float u3 = acc1[nt][2] * basB1.x + acc1[nt][3] * basB1.y;
            u0 += __shfl_xor_sync(0xFFFFFFFFu, u0, 1);
            u1 += __shfl_xor_sync(0xFFFFFFFFu, u1, 1);
            u2 += __shfl_xor_sync(0xFFFFFFFFu, u2, 1);
            u3 += __shfl_xor_sync(0xFFFFFFFFu, u3, 1);
            u0 += __shfl_xor_sync(0xFFFFFFFFu, u0, 2);
            u1 += __shfl_xor_sync(0xFFFFFFFFu, u1, 2);
            u2 += __shfl_xor_sync(0xFFFFFFFFu, u2, 2);
            u3 += __shfl_xor_sync(0xFFFFFFFFu, u3, 2);
            if ((l & 3) == 0) {
                int c_out = it * 4 + nt;
                outS[r0 * OPITCH + c_out]        = u0;
                outS[(r0 + 8) * OPITCH + c_out]  = u1;
                outS[(r0 + 16) * OPITCH + c_out] = u2;
                outS[(r0 + 24) * OPITCH + c_out] = u3;
            }
        }
    }

    // -- final coalesced store: outS[128][64] -> out --
    __syncthreads();
    #pragma unroll
    for (int i = 0; i < 16; i++) {
        int idx = tid + i * 128;              // 0..2047
        int r = idx >> 4, c4 = (idx & 15) * 4;
        float4 v = *(float4*)(outS + r * OPITCH + c4);
        *(float4*)(out + (pairbase + r) * 64 + c4) = v;
    }
}

extern "C" void kernel_launch(void* const* d_in, const int* in_sizes, int n_in,
                              void* d_out, int out_size) {
    const float* p1    = (const float*)d_in[0];
    const void*  pi    = d_in[1];
    const void*  pj    = d_in[2];
    const float* basis = (const float*)d_in[3];
    const float* W1    = (const float*)d_in[4];
    const float* W2    = (const float*)d_in[5];
    (void)in_sizes; (void)n_in; (void)out_size;

    __half* q;
    cudaGetSymbolAddress((void**)&q, g_q);

    cudaFuncSetAttribute(pil_main, cudaFuncAttributeMaxDynamicSharedMemorySize, SM_SIZE);

    pil_q<<<dim3((N_NODES + 63) / 64, 4), 256>>>(p1, W1, W2, q);
    pil_main<<<N_TILES, 128, SM_SIZE>>>(pi, pj, basis, (float*)d_out);
}

// round 14
// speedup vs baseline: 1.0557x; 1.0557x over previous
#include <cuda_runtime.h>
#include <cuda_fp16.h>

#define N_NODES   50000
#define N_PAIRS   800000
#define TILE_M    128
#define N_TILES   (N_PAIRS / TILE_M)       // 6250

// ---------------- main-kernel SMEM layout ----------------
#define PITCH     528                       // bytes per A row (256 halves + 8 pad)
#define SM_A      0                         // 128*528 = 67584 ; reused as out staging
#define SM_B      67584
#define BUF       8448                      // 16 rows * 528
#define NGROUP    16                        // 16 groups of 2 chunks (32 N-rows each)
#define OPITCH    68                        // out staging pitch in floats (272B, 16-aligned)
#define SM_SIZE   (67584 + 4 * BUF)         // 101376 -> occ 2

// ---------------- device scratch ----------------
__device__ __align__(16) __half g_q[(size_t)N_NODES * 256];   // p1 @ W1, fp16
__device__ __align__(16) __half g_w2t[512 * 256];             // W2^T as [n][k] fp16

// ---------------- helpers ----------------
__device__ __forceinline__ unsigned smem_u32(const void* p) {
    unsigned a;
    asm("{ .reg .u64 t; cvta.to.shared.u64 t, %1; cvt.u32.u64 %0, t; }" : "=r"(a) : "l"(p));
    return a;
}

__device__ __forceinline__ void ldmx4(unsigned* r, unsigned addr) {
    asm volatile("ldmatrix.sync.aligned.m8n8.x4.shared.b16 {%0,%1,%2,%3}, [%4];"
                 : "=r"(r[0]), "=r"(r[1]), "=r"(r[2]), "=r"(r[3]) : "r"(addr));
}

// fp16-accumulate HMMA, accumulate into c
__device__ __forceinline__ void mma16816h(unsigned* c, const unsigned* a, unsigned b0, unsigned b1) {
    asm volatile("mma.sync.aligned.m16n8k16.row.col.f16.f16.f16.f16 "
                 "{%0,%1}, {%2,%3,%4,%5}, {%6,%7}, {%0,%1};"
                 : "+r"(c[0]), "+r"(c[1])
                 : "r"(a[0]), "r"(a[1]), "r"(a[2]), "r"(a[3]), "r"(b0), "r"(b1));
}
// fp16-accumulate HMMA, C = 0 (segment init)
__device__ __forceinline__ void mma16816h_z(unsigned* d, const unsigned* a, unsigned b0, unsigned b1) {
    asm volatile("mma.sync.aligned.m16n8k16.row.col.f16.f16.f16.f16 "
                 "{%0,%1}, {%2,%3,%4,%5}, {%6,%7}, {%8,%8};"
                 : "=r"(d[0]), "=r"(d[1])
                 : "r"(a[0]), "r"(a[1]), "r"(a[2]), "r"(a[3]), "r"(b0), "r"(b1), "r"(0u));
}

__device__ __forceinline__ float tanh_approx(float x) {
    float r;
    asm("tanh.approx.f32 %0, %1;" : "=f"(r) : "f"(x));
    return r;
}

#define CP16(sm, g)  asm volatile("cp.async.cg.shared.global [%0], [%1], 16;" :: "r"(sm), "l"(g) : "memory")
#define CP_COMMIT()  asm volatile("cp.async.commit_group;" ::: "memory")
#define CP_WAIT0()   asm volatile("cp.async.wait_group 0;" ::: "memory")

// ---------------- kernel A: q = p1 @ W1 (fp32 math, fp16 store) + W2 prep ----------------
__global__ __launch_bounds__(256) void pil_q(const float* __restrict__ p1,
                                             const float* __restrict__ W1,
                                             const float* __restrict__ W2,
                                             __half* __restrict__ q) {
    __shared__ float sA[64 * 68];
    __shared__ float sB[64 * 68];
    int tid = threadIdx.x;
    int m0 = blockIdx.x * 64, n0 = blockIdx.y * 64;

    // fold W2^T fp16 conversion into this kernel (y==0 stripe covers all 131072 elems)
    if (blockIdx.y == 0) {
        int t = blockIdx.x * 256 + tid;            // gridDim.x*256 = 200192 >= 131072
        if (t < 512 * 256) {
            int k = t >> 9, n = t & 511;
            g_w2t[n * 256 + k] = __float2half_rn(W2[t]);
        }
    }

    #pragma unroll
    for (int i = 0; i < 4; i++) {
        int v = tid + i * 256;
        int r = v >> 4, c4 = (v & 15) * 4;
        float4 av = make_float4(0.f, 0.f, 0.f, 0.f);
        if (m0 + r < N_NODES) av = *(const float4*)(p1 + (long)(m0 + r) * 64 + c4);
        *(float4*)(sA + r * 68 + c4) = av;
        *(float4*)(sB + r * 68 + c4) = *(const float4*)(W1 + (long)r * 256 + n0 + c4);
    }
    __syncthreads();

    int tx = tid & 15, ty = tid >> 4;
    float c[4][4];
    #pragma unroll
    for (int i = 0; i < 4; i++)
        #pragma unroll
        for (int j = 0; j < 4; j++) c[i][j] = 0.f;

    #pragma unroll 8
    for (int k = 0; k < 64; k++) {
        float4 b = *(float4*)(sB + k * 68 + tx * 4);
        #pragma unroll
        for (int i = 0; i < 4; i++) {
            float a = sA[(ty * 4 + i) * 68 + k];
            c[i][0] = fmaf(a, b.x, c[i][0]);
            c[i][1] = fmaf(a, b.y, c[i][1]);
            c[i][2] = fmaf(a, b.z, c[i][2]);
            c[i][3] = fmaf(a, b.w, c[i][3]);
        }
    }
    #pragma unroll
    for (int i = 0; i < 4; i++) {
        int m = m0 + ty * 4 + i;
        if (m < N_NODES) {
            __half2 h01 = __floats2half2_rn(c[i][0], c[i][1]);
            __half2 h23 = __floats2half2_rn(c[i][2], c[i][3]);
            uint2 o;
            o.x = *(unsigned*)&h01;
            o.y = *(unsigned*)&h23;
            *(uint2*)(q + (long)m * 256 + n0 + tx * 4) = o;
        }
    }
}

// ---------------- main: gather + tanh + GEMM2 + basis einsum ----------------
// 128 threads / 4 warps; each warp owns 32 pair-rows (2 m16 tiles).
// fp16-accum HMMA (rt=8) in K=64 segments promoted to fp32; chunks processed
// sequentially within a group to keep live registers under the spill cliff.
__global__ __launch_bounds__(128, 2) void pil_main(const void* __restrict__ pi,
                                                   const void* __restrict__ pj,
                                                   const float* __restrict__ basis,
                                                   float* __restrict__ out) {
    extern __shared__ char smem[];
    unsigned sb = smem_u32(smem);
    float* outS = (float*)smem;               // overlays A region (pitch OPITCH floats)
    int tid  = threadIdx.x;
    int w    = tid >> 5;
    int l    = tid & 31;
    long pairbase = (long)blockIdx.x * TILE_M;

    // -- prefetch W2 group 0 (rows 0..31) immediately --
    {
        #pragma unroll
        for (int i = 0; i < 8; i++) {
            int v = tid + i * 128;                    // 0..1023
            int r = v >> 5, seg = (v & 31) * 16;
            CP16(sb + SM_B + r * PITCH + seg, (const char*)g_w2t + (long)r * 512 + seg);
        }
        CP_COMMIT();
    }

    // -- index dtype sniff (int64 vs silently-int32) --
    bool is64;
    {
        const unsigned* wds = (const unsigned*)pi;
        unsigned acc = 0;
        #pragma unroll
        for (int u = 1; u < 32; u += 2) acc |= wds[u];
        is64 = (acc == 0);
    }

    // -- basis fragments for epilogue: 4 rows per lane (2 m-tiles x 2 row-halves) --
    int r0 = 32 * w + (l >> 2);                 // m-tile 0, first half
    int s  = l & 3;
    float2 basA0 = *(const float2*)(basis + (pairbase + r0) * 8 + 2 * s);
    float2 basB0 = *(const float2*)(basis + (pairbase + r0 + 8) * 8 + 2 * s);
    float2 basA1 = *(const float2*)(basis + (pairbase + r0 + 16) * 8 + 2 * s);
    float2 basB1 = *(const float2*)(basis + (pairbase + r0 + 24) * 8 + 2 * s);

    // -- phase 1: gather q row (fp16), tanh.approx -> SMEM A (1 row / thread) --
    {
        int row = tid;
        long p = pairbase + row;
        long ii, jj;
        if (is64) { ii = ((const long long*)pi)[p]; jj = ((const long long*)pj)[p]; }
        else      { ii = ((const int*)pi)[p];       jj = ((const int*)pj)[p]; }
        const uint4* qi = (const uint4*)(g_q + (size_t)ii * 256);
        const uint4* qj = (const uint4*)(g_q + (size_t)jj * 256);
        char* dst = smem + row * PITCH;
        #pragma unroll 4
        for (int j = 0; j < 32; j++) {
            uint4 A = qi[j], B = qj[j];
            uint4 O;
            {
                float2 fa = __half22float2(*(__half2*)&A.x), fb = __half22float2(*(__half2*)&B.x);
                __half2 h = __floats2half2_rn(tanh_approx(fa.x + fb.x), tanh_approx(fa.y + fb.y));
                O.x = *(unsigned*)&h;
            }
            {
                float2 fa = __half22float2(*(__half2*)&A.y), fb = __half22float2(*(__half2*)&B.y);
                __half2 h = __floats2half2_rn(tanh_approx(fa.x + fb.x), tanh_approx(fa.y + fb.y));
                O.y = *(unsigned*)&h;
            }
            {
                float2 fa = __half22float2(*(__half2*)&A.z), fb = __half22float2(*(__half2*)&B.z);
                __half2 h = __floats2half2_rn(tanh_approx(fa.x + fb.x), tanh_approx(fa.y + fb.y));
                O.z = *(unsigned*)&h;
            }
            {
                float2 fa = __half22float2(*(__half2*)&A.w), fb = __half22float2(*(__half2*)&B.w);
                __half2 h = __floats2half2_rn(tanh_approx(fa.x + fb.x), tanh_approx(fa.y + fb.y));
                O.w = *(unsigned*)&h;
            }
            *(uint4*)(dst + j * 16) = O;
        }
    }
    __syncwarp();   // warp w wrote rows 32w..32w+31 == exactly its own A rows

    // -- load A fragments for both m-tiles into registers (128 regs/thread) --
    unsigned a0[16][4], a1[16][4];
    {
        unsigned rowA = 32 * w + (l & 7) + ((l >> 3) & 1) * 8;
        unsigned colA = (l >> 4) * 16;
        unsigned aBase = sb + rowA * PITCH + colA;
        #pragma unroll
        for (int ks = 0; ks < 16; ks++) ldmx4(a0[ks], aBase + ks * 32);
        #pragma unroll
        for (int ks = 0; ks < 16; ks++) ldmx4(a1[ks], aBase + 16 * PITCH + ks * 32);
    }

    // -- per-lane B ldmatrix base --
    unsigned rowBl = (l & 7) + (l >> 4) * 8;
    unsigned colBl = ((l >> 3) & 1) * 16;
    unsigned bLane = rowBl * PITCH + colBl;

    // -- phase 2: 16 groups of 2 chunks (32 N-rows), distance-1 double buffer --
    for (int it = 0; it < NGROUP; it++) {
        CP_WAIT0();               // group it resident
        __syncthreads();          // ... and other buffer pair free

        if (it + 1 < NGROUP) {    // prefetch group it+1 into the other buffer pair
            unsigned dst = sb + SM_B + ((it + 1) & 1) * (2 * BUF);
            const char* src = (const char*)g_w2t + (long)(it + 1) * 32 * 512;
            #pragma unroll
            for (int i = 0; i < 8; i++) {
                int v = tid + i * 128;                // 0..1023
                int r = v >> 5, seg = (v & 31) * 16;
                CP16(dst + r * PITCH + seg, src + (long)r * 512 + seg);
            }
            CP_COMMIT();
        }

        float acc0[4][4], acc1[4][4];                 // fp32 accumulators [nt][frag]
        #pragma unroll
        for (int n = 0; n < 4; n++)
            #pragma unroll
            for (int j = 0; j < 4; j++) { acc0[n][j] = 0.f; acc1[n][j] = 0.f; }

        // process the 2 chunks of the group sequentially (low register pressure)
        #pragma unroll
        for (int nb = 0; nb < 2; nb++) {
            unsigned bB = sb + SM_B + (it & 1) * (2 * BUF) + nb * BUF + bLane;
            // 4 segments of K=64: fp16 accumulate 4 HMMAs, then promote to fp32
            #pragma unroll
            for (int sg = 0; sg < 4; sg++) {
                unsigned c00[2], c01[2], c10[2], c11[2];   // [mtile][n8tile]
                {   // kk = 0: init (C = 0)
                    int ks = sg * 4;
                    unsigned bb[4];
                    ldmx4(bb, bB + ks * 32);
                    mma16816h_z(c00, a0[ks], bb[0], bb[1]);
                    mma16816h_z(c01, a0[ks], bb[2], bb[3]);
                    mma16816h_z(c10, a1[ks], bb[0], bb[1]);
                    mma16816h_z(c11, a1[ks], bb[2], bb[3]);
                }
                #pragma unroll
                for (int kk = 1; kk < 4; kk++) {
                    int ks = sg * 4 + kk;
                    unsigned bb[4];
                    ldmx4(bb, bB + ks * 32);
                    mma16816h(c00, a0[ks], bb[0], bb[1]);
                    mma16816h(c01, a0[ks], bb[2], bb[3]);
                    mma16816h(c10, a1[ks], bb[0], bb[1]);
                    mma16816h(c11, a1[ks], bb[2], bb[3]);
                }
                // promote fp16 partials into fp32 accumulators
                int n0i = nb * 2, n1i = nb * 2 + 1;
                float2 f;
                f = __half22float2(*(__half2*)&c00[0]); acc0[n0i][0] += f.x; acc0[n0i][1] += f.y;
                f = __half22float2(*(__half2*)&c00[1]); acc0[n0i][2] += f.x; acc0[n0i][3] += f.y;
                f = __half22float2(*(__half2*)&c01[0]); acc0[n1i][0] += f.x; acc0[n1i][1] += f.y;
                f = __half22float2(*(__half2*)&c01[1]); acc0[n1i][2] += f.x; acc0[n1i][3] += f.y;
                f = __half22float2(*(__half2*)&c10[0]); acc1[n0i][0] += f.x; acc1[n0i][1] += f.y;
                f = __half22float2(*(__half2*)&c10[1]); acc1[n0i][2] += f.x; acc1[n0i][3] += f.y;
                f = __half22float2(*(__half2*)&c11[0]); acc1[n1i][0] += f.x; acc1[n1i][1] += f.y;
                f = __half22float2(*(__half2*)&c11[1]); acc1[n1i][2] += f.x; acc1[n1i][3] += f.y;
            }
        }

        // epilogue: fold basis, reduce lane quads, stage into outS (A region, now dead)
        #pragma unroll
        for (int nt = 0; nt < 4; nt++) {
            float u0 = acc0[nt][0] * basA0.x + acc0[nt][1] * basA0.y;
            float u1 = acc0[nt][2] * basB0.x + acc0[nt][3] * basB0.y;
            float u2 = acc1[nt][0] * basA1.x + acc1[nt][1] * basA1.y;
            float u3 = acc1[nt][2] * basB1.x + acc1[nt][3] * basB1.y;
            u0 += __shfl_xor_sync(0xFFFFFFFFu, u0, 1);
            u1 += __shfl_xor_sync(0xFFFFFFFFu, u1, 1);
            u2 += __shfl_xor_sync(0xFFFFFFFFu, u2, 1);
            u3 += __shfl_xor_sync(0xFFFFFFFFu, u3, 1);
            u0 += __shfl_xor_sync(0xFFFFFFFFu, u0, 2);
            u1 += __shfl_xor_sync(0xFFFFFFFFu, u1, 2);
            u2 += __shfl_xor_sync(0xFFFFFFFFu, u2, 2);
            u3 += __shfl_xor_sync(0xFFFFFFFFu, u3, 2);
            if ((l & 3) == 0) {
                int c_out = it * 4 + nt;
                outS[r0 * OPITCH + c_out]        = u0;
                outS[(r0 + 8) * OPITCH + c_out]  = u1;
                outS[(r0 + 16) * OPITCH + c_out] = u2;
                outS[(r0 + 24) * OPITCH + c_out] = u3;
            }
        }
    }

    // -- final coalesced store: outS[128][64] -> out --
    __syncthreads();
    #pragma unroll
    for (int i = 0; i < 16; i++) {
        int idx = tid + i * 128;              // 0..2047
        int r = idx >> 4, c4 = (idx & 15) * 4;
        float4 v = *(float4*)(outS + r * OPITCH + c4);
        *(float4*)(out + (pairbase + r) * 64 + c4) = v;
    }
}

extern "C" void kernel_launch(void* const* d_in, const int* in_sizes, int n_in,
                              void* d_out, int out_size) {
    const float* p1    = (const float*)d_in[0];
    const void*  pi    = d_in[1];
    const void*  pj    = d_in[2];
    const float* basis = (const float*)d_in[3];
    const float* W1    = (const float*)d_in[4];
    const float* W2    = (const float*)d_in[5];
    (void)in_sizes; (void)n_in; (void)out_size;

    __half* q;
    cudaGetSymbolAddress((void**)&q, g_q);

    cudaFuncSetAttribute(pil_main, cudaFuncAttributeMaxDynamicSharedMemorySize, SM_SIZE);

    pil_q<<<dim3((N_NODES + 63) / 64, 4), 256>>>(p1, W1, W2, q);
    pil_main<<<N_TILES, 128, SM_SIZE>>>(pi, pj, basis, (float*)d_out);
}